// round 14
// baseline (speedup 1.0000x reference)
#include <cuda_runtime.h>
#include <cuda_bf16.h>
#include <cuda_fp16.h>
#include <math.h>

#define NN 50000
#define EE 800000
#define RR 2000
#define FF 128
#define FDD 384
#define PP 64

// ---------------- scratch (device globals; no allocation allowed) ----------
__device__ int   g_deg[NN];
__device__ int   g_rowptr[NN + 1];
__device__ int   g_pos[NN];
__device__ int   g_bsum[64];
__device__ int   g_srcS[EE];
__device__ int   g_relS[EE];
__device__ __align__(16) float g_rhat[RR * FF];
__device__ float g_sc[4 * RR];
__device__ __align__(16) float g_outE[(size_t)NN * FDD];
__device__ __align__(16) float g_outR[(size_t)NN * FDD];
__device__ __align__(16) float g_pf[2 * (size_t)NN * FDD];
__device__ __align__(16) float g_phNT[2 * FDD * PP];
__device__ __align__(16) __half g_pf16[2 * (size_t)NN * FDD];
__device__ __align__(16) __half g_Bt16[2 * FDD * FDD];

// ---------------- generic helpers -------------------------------------------
__device__ __forceinline__ unsigned smem_u32(const void* p) {
    unsigned a;
    asm("{ .reg .u64 t; cvta.to.shared.u64 t, %1; cvt.u32.u64 %0, t; }" : "=r"(a) : "l"(p));
    return a;
}
__device__ __forceinline__ float warpSum(float v) {
#pragma unroll
    for (int o = 16; o; o >>= 1) v += __shfl_xor_sync(0xffffffffu, v, o);
    return v;
}
__device__ __forceinline__ void warpSum4(float& a, float& b, float& c, float& d) {
#pragma unroll
    for (int o = 16; o; o >>= 1) {
        a += __shfl_xor_sync(0xffffffffu, a, o);
        b += __shfl_xor_sync(0xffffffffu, b, o);
        c += __shfl_xor_sync(0xffffffffu, c, o);
        d += __shfl_xor_sync(0xffffffffu, d, o);
    }
}
__device__ __forceinline__ float warpMax(float v) {
#pragma unroll
    for (int o = 16; o; o >>= 1) v = fmaxf(v, __shfl_xor_sync(0xffffffffu, v, o));
    return v;
}
__device__ __forceinline__ float dot4(float4 a, float4 b) {
    return a.x * b.x + a.y * b.y + a.z * b.z + a.w * b.w;
}
__device__ __forceinline__ void sth4(__half* p, float4 v) {
    uint2 raw;
    *(__half2*)&raw.x = __float22half2_rn(make_float2(v.x, v.y));
    *(__half2*)&raw.y = __float22half2_rn(make_float2(v.z, v.w));
    *(uint2*)p = raw;
}
__device__ __forceinline__ void add4(float4& a, float4 b) {
    a.x += b.x; a.y += b.y; a.z += b.z; a.w += b.w;
}

// ---------------- CSR build -------------------------------------------------
__global__ void k_zero() {
    int i = blockIdx.x * blockDim.x + threadIdx.x;
    if (i < NN) g_deg[i] = 0;
}
__global__ void k_count(const int* __restrict__ dst) {
    int i = blockIdx.x * blockDim.x + threadIdx.x;
    if (i < EE) atomicAdd(&g_deg[dst[i]], 1);
}
__global__ void k_scan1() {
    __shared__ int s[1024];
    int i = blockIdx.x * 1024 + threadIdx.x;
    int v = (i < NN) ? g_deg[i] : 0;
    s[threadIdx.x] = v;
    __syncthreads();
#pragma unroll
    for (int off = 1; off < 1024; off <<= 1) {
        int t = (threadIdx.x >= off) ? s[threadIdx.x - off] : 0;
        __syncthreads();
        s[threadIdx.x] += t;
        __syncthreads();
    }
    if (i < NN) g_rowptr[i + 1] = s[threadIdx.x];
    if (threadIdx.x == 1023) g_bsum[blockIdx.x] = s[1023];
}
__global__ void k_scan2(int nb) {
    if (threadIdx.x == 0) {
        int run = 0;
        for (int b = 0; b < nb; b++) { int t = g_bsum[b]; g_bsum[b] = run; run += t; }
    }
}
__global__ void k_scan3() {
    int i = blockIdx.x * 1024 + threadIdx.x;
    if (i < NN) {
        int incl = g_rowptr[i + 1] + g_bsum[blockIdx.x];
        g_rowptr[i + 1] = incl;
        g_pos[i] = incl - g_deg[i];
    }
    if (i == 0) g_rowptr[0] = 0;
}
__global__ void k_fill(const int* __restrict__ src, const int* __restrict__ dst,
                       const int* __restrict__ rel) {
    int i = blockIdx.x * blockDim.x + threadIdx.x;
    if (i < EE) {
        int p = atomicAdd(&g_pos[dst[i]], 1);
        g_srcS[p] = src[i];
        g_relS[p] = rel[i];
    }
}

// ---------------- per-relation precompute ----------------------------------
__global__ void k_rhat(const float* __restrict__ rel_emb) {
    __shared__ float red[4];
    int r = blockIdx.x, t = threadIdx.x;
    float v = rel_emb[r * FF + t];
    float ss = warpSum(v * v);
    if ((t & 31) == 0) red[t >> 5] = ss;
    __syncthreads();
    float tot = red[0] + red[1] + red[2] + red[3];
    float invn = 1.0f / fmaxf(sqrtf(tot), 1e-12f);
    g_rhat[r * FF + t] = v * invn;
}
__global__ void k_scores(const float* __restrict__ ae, const float* __restrict__ ar) {
    int w = (blockIdx.x * blockDim.x + threadIdx.x) >> 5;
    int lane = threadIdx.x & 31;
    if (w >= 4 * RR) return;
    int t = w / RR, r = w % RR;
    const float* attn = ((t < 2) ? ae : ar) + (t & 1) * FF;
    float4 u = *(const float4*)&g_rhat[r * FF + lane * 4];
    float4 a = *(const float4*)&attn[lane * 4];
    float d = warpSum(dot4(u, a));
    if (lane == 0) g_sc[t * RR + r] = d;
}

// ---------------- gate kernel -> transposed fp16 -----------------------------
__global__ void k_cvtB(const float* __restrict__ ge, const float* __restrict__ gr) {
    int i = blockIdx.x * blockDim.x + threadIdx.x;
    if (i >= FDD * FDD) return;
    int k = i / FDD, n = i % FDD;
    g_Bt16[n * FDD + k] = __float2half(ge[i]);
    g_Bt16[FDD * FDD + n * FDD + k] = __float2half(gr[i]);
}

// ---------------- initial features: 2 warps per node ------------------------
__global__ void __launch_bounds__(256) k_init(const float* __restrict__ ent,
                                              const float* __restrict__ rel) {
    __shared__ float4 sE[4][32];
    __shared__ float4 sR[4][32];
    int warp = threadIdx.x >> 5, lane = threadIdx.x & 31;
    int slot = warp >> 1, half = warp & 1;
    int w = blockIdx.x * 4 + slot;            // NN % 4 == 0, always valid
    int b = g_rowptr[w], e = g_rowptr[w + 1];
    float4 aE = make_float4(0, 0, 0, 0), aR = make_float4(0, 0, 0, 0);
    int i = b + half;
    for (; i + 2 < e; i += 4) {
        int s0 = g_srcS[i],     r0 = g_relS[i];
        int s1 = g_srcS[i + 2], r1 = g_relS[i + 2];
        float4 h0 = *(const float4*)&ent[(size_t)s0 * FF + lane * 4];
        float4 g0 = *(const float4*)&rel[(size_t)r0 * FF + lane * 4];
        float4 h1 = *(const float4*)&ent[(size_t)s1 * FF + lane * 4];
        float4 g1 = *(const float4*)&rel[(size_t)r1 * FF + lane * 4];
        add4(aE, h0); add4(aR, g0);
        add4(aE, h1); add4(aR, g1);
    }
    if (i < e) {
        int s = g_srcS[i], r = g_relS[i];
        add4(aE, *(const float4*)&ent[(size_t)s * FF + lane * 4]);
        add4(aR, *(const float4*)&rel[(size_t)r * FF + lane * 4]);
    }
    if (half == 1) { sE[slot][lane] = aE; sR[slot][lane] = aR; }
    __syncthreads();
    if (half == 0) {
        add4(aE, sE[slot][lane]);
        add4(aR, sR[slot][lane]);
        float inv = 1.0f / fmaxf((float)(e - b), 1.0f);
        float4 oE = make_float4(tanhf(aE.x * inv), tanhf(aE.y * inv), tanhf(aE.z * inv), tanhf(aE.w * inv));
        float4 oR = make_float4(tanhf(aR.x * inv), tanhf(aR.y * inv), tanhf(aR.z * inv), tanhf(aR.w * inv));
        *(float4*)&g_outE[(size_t)w * FDD + lane * 4] = oE;
        *(float4*)&g_outR[(size_t)w * FDD + lane * 4] = oR;
    }
}

// ---------------- fused dual-layer aggregation: 2 warps per node ------------
__device__ __forceinline__ void edgeUpdate(float4 h, float4 u, float d, float wgt,
                                           float4& acc) {
    float c = 2.0f * d * wgt;
    acc.x += wgt * h.x - c * u.x;
    acc.y += wgt * h.y - c * u.y;
    acc.z += wgt * h.z - c * u.z;
    acc.w += wgt * h.w - c * u.w;
}

__global__ void __launch_bounds__(256) k_agg2(int layer) {
    __shared__ float4 sE[4][32];
    __shared__ float4 sR[4][32];
    __shared__ float  sWsE[4], sWsR[4];
    __shared__ float  sME[4][2], sMR[4][2];
    int warp = threadIdx.x >> 5, lane = threadIdx.x & 31;
    int slot = warp >> 1, half = warp & 1;
    int w = blockIdx.x * 4 + slot;            // NN % 4 == 0
    const float* finE = g_outE + layer * FF;
    float*       foutE = g_outE + (layer + 1) * FF;
    const float* finR = g_outR + layer * FF;
    float*       foutR = g_outR + (layer + 1) * FF;
    const float* scE = g_sc + layer * RR;
    const float* scR = g_sc + (2 + layer) * RR;
    int b = g_rowptr[w], e = g_rowptr[w + 1];
    // partial max over this warp's edge subset (i ≡ half mod 2), lane-strided
    float mE = -1e30f, mR = -1e30f;
    for (int i = b + half + 2 * lane; i < e; i += 64) {
        int r = g_relS[i];
        mE = fmaxf(mE, scE[r]);
        mR = fmaxf(mR, scR[r]);
    }
    mE = warpMax(mE); mR = warpMax(mR);
    if (lane == 0) { sME[slot][half] = mE; sMR[slot][half] = mR; }
    __syncthreads();
    mE = fmaxf(sME[slot][0], sME[slot][1]);
    mR = fmaxf(sMR[slot][0], sMR[slot][1]);
    // main loop: this warp's edges with 2-edge ILP
    float4 aE = make_float4(0, 0, 0, 0), aR = make_float4(0, 0, 0, 0);
    float wsE = 0.0f, wsR = 0.0f;
    int i = b + half;
    for (; i + 2 < e; i += 4) {
        int s0 = g_srcS[i],     r0 = g_relS[i];
        int s1 = g_srcS[i + 2], r1 = g_relS[i + 2];
        float4 u0  = *(const float4*)&g_rhat[(size_t)r0 * FF + lane * 4];
        float4 u1  = *(const float4*)&g_rhat[(size_t)r1 * FF + lane * 4];
        float4 h0E = *(const float4*)&finE[(size_t)s0 * FDD + lane * 4];
        float4 h1E = *(const float4*)&finE[(size_t)s1 * FDD + lane * 4];
        float4 h0R = *(const float4*)&finR[(size_t)s0 * FDD + lane * 4];
        float4 h1R = *(const float4*)&finR[(size_t)s1 * FDD + lane * 4];
        float d0E = dot4(h0E, u0), d0R = dot4(h0R, u0);
        float d1E = dot4(h1E, u1), d1R = dot4(h1R, u1);
        warpSum4(d0E, d0R, d1E, d1R);
        float w0E = __expf(scE[r0] - mE), w0R = __expf(scR[r0] - mR);
        float w1E = __expf(scE[r1] - mE), w1R = __expf(scR[r1] - mR);
        wsE += w0E; wsR += w0R;
        edgeUpdate(h0E, u0, d0E, w0E, aE);
        edgeUpdate(h0R, u0, d0R, w0R, aR);
        wsE += w1E; wsR += w1R;
        edgeUpdate(h1E, u1, d1E, w1E, aE);
        edgeUpdate(h1R, u1, d1R, w1R, aR);
    }
    if (i < e) {
        int s = g_srcS[i], r = g_relS[i];
        float4 u  = *(const float4*)&g_rhat[(size_t)r * FF + lane * 4];
        float4 hE = *(const float4*)&finE[(size_t)s * FDD + lane * 4];
        float4 hR = *(const float4*)&finR[(size_t)s * FDD + lane * 4];
        float dE = dot4(hE, u), dR = dot4(hR, u);
        float z0 = 0.0f, z1 = 0.0f;
        warpSum4(dE, dR, z0, z1);
        float wE = __expf(scE[r] - mE);
        float wR = __expf(scR[r] - mR);
        wsE += wE; wsR += wR;
        edgeUpdate(hE, u, dE, wE, aE);
        edgeUpdate(hR, u, dR, wR, aR);
    }
    // combine the two halves
    if (half == 1) {
        sE[slot][lane] = aE; sR[slot][lane] = aR;
        if (lane == 0) { sWsE[slot] = wsE; sWsR[slot] = wsR; }
    }
    __syncthreads();
    if (half == 0) {
        add4(aE, sE[slot][lane]);
        add4(aR, sR[slot][lane]);
        wsE += sWsE[slot];
        wsR += sWsR[slot];
        float iE = (e > b) ? (1.0f / wsE) : 0.0f;
        float iR = (e > b) ? (1.0f / wsR) : 0.0f;
        float4 oE = make_float4(tanhf(aE.x * iE), tanhf(aE.y * iE), tanhf(aE.z * iE), tanhf(aE.w * iE));
        float4 oR = make_float4(tanhf(aR.x * iR), tanhf(aR.y * iR), tanhf(aR.z * iR), tanhf(aR.w * iR));
        *(float4*)&foutE[(size_t)w * FDD + lane * 4] = oE;
        *(float4*)&foutR[(size_t)w * FDD + lane * 4] = oR;
    }
}

// ---------------- normalized proxy -> transposed, both duals ----------------
__global__ void k_phN(const float* __restrict__ proxy_e, const float* __restrict__ proxy_r) {
    __shared__ float red[4];
    int p = blockIdx.x, t = threadIdx.x;
    int dual = blockIdx.y;
    const float* proxy = dual ? proxy_r : proxy_e;
    float* phNT = g_phNT + dual * FDD * PP;
    float v0 = proxy[p * FDD + t];
    float v1 = proxy[p * FDD + 128 + t];
    float v2 = proxy[p * FDD + 256 + t];
    float ss = warpSum(v0 * v0 + v1 * v1 + v2 * v2);
    if ((t & 31) == 0) red[t >> 5] = ss;
    __syncthreads();
    float tot = red[0] + red[1] + red[2] + red[3];
    float invn = 1.0f / fmaxf(sqrtf(tot), 1e-12f);
    phNT[t * PP + p]         = v0 * invn;
    phNT[(128 + t) * PP + p] = v1 * invn;
    phNT[(256 + t) * PP + p] = v2 * invn;
}

// ---------------- fused proxy attention + proxy feature, both duals ---------
__global__ void k_prox(const float* __restrict__ proxy_e, const float* __restrict__ proxy_r) {
    __shared__ float so[8][4][FDD];   // 48 KB
    int warp = threadIdx.x >> 5, lane = threadIdx.x & 31;
    int n0 = (blockIdx.x * 8 + warp) * 4;
    int dualSel = blockIdx.y;
    const float* proxy = dualSel ? proxy_r : proxy_e;
    const float* Of = dualSel ? g_outR : g_outE;
    size_t doff = (size_t)dualSel * NN * FDD;
    float invn[4];
#pragma unroll
    for (int rr = 0; rr < 4; rr++) {
        int n = n0 + rr;
        float ss = 0.0f;
        if (n < NN) {
#pragma unroll
            for (int c = 0; c < 3; c++) {
                float4 v = *(const float4*)&Of[(size_t)n * FDD + c * 128 + lane * 4];
                *(float4*)&so[warp][rr][c * 128 + lane * 4] = v;
                ss += dot4(v, v);
            }
        }
        ss = warpSum(ss);
        invn[rr] = 1.0f / fmaxf(sqrtf(ss), 1e-12f);
    }
    __syncwarp();
    const float2* phT = (const float2*)(g_phNT + dualSel * FDD * PP);
    float2 l[4];
#pragma unroll
    for (int rr = 0; rr < 4; rr++) l[rr] = make_float2(0.0f, 0.0f);
    for (int j = 0; j < FDD; j += 4) {
#pragma unroll
        for (int jj = 0; jj < 4; jj++) {
            float2 q = phT[(j + jj) * 32 + lane];
#pragma unroll
            for (int rr = 0; rr < 4; rr++) {
                float s = so[warp][rr][j + jj];
                l[rr].x += s * q.x;
                l[rr].y += s * q.y;
            }
        }
    }
    float2 at2[4];
#pragma unroll
    for (int rr = 0; rr < 4; rr++) {
        float a0 = l[rr].x * invn[rr], a1 = l[rr].y * invn[rr];
        float m = warpMax(fmaxf(a0, a1));
        float w0 = __expf(a0 - m), w1 = __expf(a1 - m);
        float is = 1.0f / warpSum(w0 + w1);
        at2[rr] = make_float2(w0 * is, w1 * is);
    }
    float4 acc[4][3];
#pragma unroll
    for (int rr = 0; rr < 4; rr++)
#pragma unroll
        for (int c = 0; c < 3; c++)
            acc[rr][c] = *(const float4*)&so[warp][rr][c * 128 + lane * 4];
#pragma unroll 16
    for (int p = 0; p < PP; p++) {
        const float* pr = proxy + p * FDD;
        float4 q0 = *(const float4*)&pr[lane * 4];
        float4 q1 = *(const float4*)&pr[128 + lane * 4];
        float4 q2 = *(const float4*)&pr[256 + lane * 4];
        int srcLane = p >> 1;
#pragma unroll
        for (int rr = 0; rr < 4; rr++) {
            float comp = (p & 1) ? at2[rr].y : at2[rr].x;
            float av = __shfl_sync(0xffffffffu, comp, srcLane);
            acc[rr][0].x -= av * q0.x; acc[rr][0].y -= av * q0.y;
            acc[rr][0].z -= av * q0.z; acc[rr][0].w -= av * q0.w;
            acc[rr][1].x -= av * q1.x; acc[rr][1].y -= av * q1.y;
            acc[rr][1].z -= av * q1.z; acc[rr][1].w -= av * q1.w;
            acc[rr][2].x -= av * q2.x; acc[rr][2].y -= av * q2.y;
            acc[rr][2].z -= av * q2.z; acc[rr][2].w -= av * q2.w;
        }
    }
#pragma unroll
    for (int rr = 0; rr < 4; rr++) {
        int n = n0 + rr;
        if (n < NN) {
#pragma unroll
            for (int c = 0; c < 3; c++) {
                size_t idx = (size_t)n * FDD + c * 128 + lane * 4;
                *(float4*)&g_pf[doff + idx] = acc[rr][c];
                sth4(&g_pf16[doff + idx], acc[rr][c]);
            }
        }
    }
}

// ---------------- HMMA gate GEMM: single-term fp16, both duals --------------
__device__ __forceinline__ float gateCombine(float t, float b, float o, float p) {
    float g = 1.0f / (1.0f + __expf(-(t + b)));
    return g * o + (1.0f - g) * p;
}

#define STRD 72
#define TSZ  (128 * STRD)
#define STAGEB (2 * TSZ * 2)              // 2 tiles = 36864 B
#define GSM_BYTES (2 * STAGEB)            // 73728 B
#define ESTRD 132

#define LDM4(r, addr) \
    asm volatile("ldmatrix.sync.aligned.m8n8.x4.shared.b16 {%0,%1,%2,%3}, [%4];" \
        : "=r"((r)[0]), "=r"((r)[1]), "=r"((r)[2]), "=r"((r)[3]) : "r"(addr))

#define CP_COMMIT() asm volatile("cp.async.commit_group;" ::: "memory")
#define CP_WAIT(n)  asm volatile("cp.async.wait_group %0;" :: "n"(n) : "memory")

__device__ __forceinline__ void cpAsync16(unsigned dst, const void* src, bool pred) {
    int sz = pred ? 16 : 0;
    asm volatile("cp.async.ca.shared.global [%0], [%1], 16, %2;"
                 :: "r"(dst), "l"(src), "r"(sz) : "memory");
}

__device__ __forceinline__ void mma16816h(float* c, const unsigned* a, const unsigned* b) {
    asm volatile(
        "mma.sync.aligned.m16n8k16.row.col.f32.f16.f16.f32 "
        "{%0,%1,%2,%3}, {%4,%5,%6,%7}, {%8,%9}, {%0,%1,%2,%3};"
        : "+f"(c[0]), "+f"(c[1]), "+f"(c[2]), "+f"(c[3])
        : "r"(a[0]), "r"(a[1]), "r"(a[2]), "r"(a[3]), "r"(b[0]), "r"(b[1]));
}

__device__ __forceinline__ void cpTile(unsigned sbase,
                                       const __half* __restrict__ src,
                                       int row0, int rowCap, int col0) {
#pragma unroll
    for (int it = 0; it < 2; it++) {
        int id = threadIdx.x + it * 512;
        int r = id >> 3, c = id & 7;
        int gr = row0 + r;
        bool ok = gr < rowCap;
        int grc = ok ? gr : 0;
        cpAsync16(sbase + (unsigned)((r * STRD + c * 8) * 2),
                  src + (size_t)grc * FDD + col0 + c * 8, ok);
    }
}

__global__ void __launch_bounds__(512, 1) k_gemm4(const float* __restrict__ bias_e,
                                                  const float* __restrict__ bias_r,
                                                  float* __restrict__ out) {
    extern __shared__ __half sm[];
    unsigned smb = smem_u32(sm);
    int tid = threadIdx.x, wid = tid >> 5, lane = tid & 31;
    int m0 = blockIdx.x * 128, j0 = blockIdx.y * 128;
    int dualSel = blockIdx.z;
    const float* bias = dualSel ? bias_r : bias_e;
    size_t doff = (size_t)dualSel * NN * FDD;
    const __half* A16 = g_pf16 + doff;
    const __half* B16 = g_Bt16 + (size_t)dualSel * FDD * FDD;
    int wm = wid & 3, wn = wid >> 2;

    unsigned aRow = (unsigned)(wm * 32 + (lane & 15));
    unsigned aCol = (unsigned)((lane >> 4) * 8);
    unsigned bRow = (unsigned)(wn * 32 + (lane & 7) + ((lane >> 4) * 8));
    unsigned bCol = (unsigned)(((lane >> 3) & 1) * 8);
    unsigned offA = (aRow * STRD + aCol) * 2;
    unsigned offB = (bRow * STRD + bCol) * 2;

    float acc[2][4][4];
#pragma unroll
    for (int mt = 0; mt < 2; mt++)
#pragma unroll
        for (int nt = 0; nt < 4; nt++)
#pragma unroll
            for (int q = 0; q < 4; q++) acc[mt][nt][q] = 0.0f;

    {
        unsigned sb = smb;
        cpTile(sb + 0 * TSZ * 2, A16, m0, NN, 0);
        cpTile(sb + 1 * TSZ * 2, B16, j0, FDD, 0);
        CP_COMMIT();
    }

    for (int kc = 0; kc < 6; kc++) {
        int s = kc & 1;
        if (kc + 1 < 6) {
            unsigned sb = smb + (unsigned)((s ^ 1) * STAGEB);
            int col0 = (kc + 1) * 64;
            cpTile(sb + 0 * TSZ * 2, A16, m0, NN, col0);
            cpTile(sb + 1 * TSZ * 2, B16, j0, FDD, col0);
            CP_COMMIT();
            CP_WAIT(1);
        } else {
            CP_WAIT(0);
        }
        __syncthreads();

        unsigned sb = smb + (unsigned)(s * STAGEB);
        unsigned baseA = sb, baseB = sb + TSZ * 2;
#pragma unroll
        for (int ks = 0; ks < 4; ks++) {
            unsigned kb = (unsigned)(ks * 32);
            unsigned a[2][4], bf[4][2];
#pragma unroll
            for (int mt = 0; mt < 2; mt++)
                LDM4(a[mt], baseA + offA + (unsigned)(mt * 16 * STRD * 2) + kb);
#pragma unroll
            for (int p = 0; p < 2; p++) {
                unsigned r[4];
                LDM4(r, baseB + offB + (unsigned)(p * 16 * STRD * 2) + kb);
                bf[2 * p][0] = r[0]; bf[2 * p][1] = r[1];
                bf[2 * p + 1][0] = r[2]; bf[2 * p + 1][1] = r[3];
            }
#pragma unroll
            for (int mt = 0; mt < 2; mt++)
#pragma unroll
                for (int nt = 0; nt < 4; nt++)
                    mma16816h(acc[mt][nt], a[mt], bf[nt]);
        }
        __syncthreads();
    }

    float* sT = (float*)sm;
    int lr = lane >> 2, lc = lane & 3;
#pragma unroll
    for (int mt = 0; mt < 2; mt++)
#pragma unroll
        for (int h = 0; h < 2; h++) {
            int rowl = wm * 32 + mt * 16 + lr + h * 8;
#pragma unroll
            for (int nt = 0; nt < 4; nt++) {
                int coll = wn * 32 + nt * 8 + lc * 2;
                *(float2*)&sT[rowl * ESTRD + coll] =
                    make_float2(acc[mt][nt][h * 2 + 0], acc[mt][nt][h * 2 + 1]);
            }
        }
    __syncthreads();

    const float* O = dualSel ? g_outR : g_outE;
    float4 b4 = *(const float4*)&bias[j0 + lane * 4];
#pragma unroll
    for (int rr = 0; rr < 8; rr++) {
        int rowl = wid * 8 + rr;
        int row = m0 + rowl;
        if (row < NN) {
            int col = j0 + lane * 4;
            float4 t4 = *(const float4*)&sT[rowl * ESTRD + lane * 4];
            float4 o4 = *(const float4*)&O[(size_t)row * FDD + col];
            float4 p4 = *(const float4*)&g_pf[doff + (size_t)row * FDD + col];
            float4 r;
            r.x = gateCombine(t4.x, b4.x, o4.x, p4.x);
            r.y = gateCombine(t4.y, b4.y, o4.y, p4.y);
            r.z = gateCombine(t4.z, b4.z, o4.z, p4.z);
            r.w = gateCombine(t4.w, b4.w, o4.w, p4.w);
            *(float4*)&out[(size_t)row * (2 * FDD) + dualSel * FDD + col] = r;
        }
    }
}

// ---------------- launch -----------------------------------------------------
extern "C" void kernel_launch(void* const* d_in, const int* in_sizes, int n_in,
                              void* d_out, int out_size) {
    const float* ent     = (const float*)d_in[0];
    const float* rel     = (const float*)d_in[1];
    const int*   esrc    = (const int*)d_in[2];
    const int*   edst    = (const int*)d_in[3];
    const int*   erel    = (const int*)d_in[4];
    const float* attn_e  = (const float*)d_in[5];
    const float* gate_e  = (const float*)d_in[6];
    const float* proxy_e = (const float*)d_in[7];
    const float* bias_e  = (const float*)d_in[8];
    const float* attn_r  = (const float*)d_in[9];
    const float* gate_r  = (const float*)d_in[10];
    const float* proxy_r = (const float*)d_in[11];
    const float* bias_r  = (const float*)d_in[12];
    float* out = (float*)d_out;

    cudaFuncSetAttribute(k_gemm4, cudaFuncAttributeMaxDynamicSharedMemorySize, GSM_BYTES);

    const int nb = (NN + 1023) / 1024;
    k_zero<<<(NN + 255) / 256, 256>>>();
    k_count<<<(EE + 255) / 256, 256>>>(edst);
    k_scan1<<<nb, 1024>>>();
    k_scan2<<<1, 32>>>(nb);
    k_scan3<<<nb, 1024>>>();
    k_fill<<<(EE + 255) / 256, 256>>>(esrc, edst, erel);
    k_rhat<<<RR, 128>>>(rel);
    k_scores<<<(4 * RR * 32 + 255) / 256, 256>>>(attn_e, attn_r);
    k_cvtB<<<(FDD * FDD + 255) / 256, 256>>>(gate_e, gate_r);
    k_phN<<<dim3(PP, 2), 128>>>(proxy_e, proxy_r);
    k_init<<<NN / 4, 256>>>(ent, rel);
    k_agg2<<<NN / 4, 256>>>(0);
    k_agg2<<<NN / 4, 256>>>(1);

    const int nwb = (NN / 4 + 7) / 8;
    k_prox<<<dim3(nwb, 2), 256>>>(proxy_e, proxy_r);
    k_gemm4<<<dim3((NN + 127) / 128, FDD / 128, 2), 512, GSM_BYTES>>>(bias_e, bias_r, out);
}

// round 15
// speedup vs baseline: 1.3910x; 1.3910x over previous
#include <cuda_runtime.h>
#include <cuda_bf16.h>
#include <cuda_fp16.h>
#include <math.h>

#define NN 50000
#define EE 800000
#define RR 2000
#define FF 128
#define FDD 384
#define PP 64

// ---------------- scratch (device globals; no allocation allowed) ----------
__device__ int   g_deg[NN];
__device__ int   g_rowptr[NN + 1];
__device__ int   g_pos[NN];
__device__ int   g_bsum[64];
__device__ int   g_srcS[EE];
__device__ int   g_relS[EE];
__device__ __align__(16) float g_rhat[RR * FF];
__device__ float g_sc[4 * RR];
__device__ __align__(16) float g_outE[(size_t)NN * FDD];
__device__ __align__(16) float g_outR[(size_t)NN * FDD];
__device__ __align__(16) float g_pf[2 * (size_t)NN * FDD];
__device__ float g_invn[2 * NN];
__device__ __align__(16) __half g_o16[2][(size_t)NN * FDD];
__device__ __align__(16) __half g_att16[2 * (size_t)NN * PP];
__device__ __align__(16) __half g_phN16[2 * PP * FDD];
__device__ __align__(16) __half g_prT16[2 * FDD * PP];
__device__ __align__(16) __half g_pf16[2 * (size_t)NN * FDD];
__device__ __align__(16) __half g_Bt16[2 * FDD * FDD];

// ---------------- generic helpers -------------------------------------------
__device__ __forceinline__ unsigned smem_u32(const void* p) {
    unsigned a;
    asm("{ .reg .u64 t; cvta.to.shared.u64 t, %1; cvt.u32.u64 %0, t; }" : "=r"(a) : "l"(p));
    return a;
}
__device__ __forceinline__ float warpSum(float v) {
#pragma unroll
    for (int o = 16; o; o >>= 1) v += __shfl_xor_sync(0xffffffffu, v, o);
    return v;
}
__device__ __forceinline__ void warpSum4(float& a, float& b, float& c, float& d) {
#pragma unroll
    for (int o = 16; o; o >>= 1) {
        a += __shfl_xor_sync(0xffffffffu, a, o);
        b += __shfl_xor_sync(0xffffffffu, b, o);
        c += __shfl_xor_sync(0xffffffffu, c, o);
        d += __shfl_xor_sync(0xffffffffu, d, o);
    }
}
__device__ __forceinline__ float warpMax(float v) {
#pragma unroll
    for (int o = 16; o; o >>= 1) v = fmaxf(v, __shfl_xor_sync(0xffffffffu, v, o));
    return v;
}
__device__ __forceinline__ float dot4(float4 a, float4 b) {
    return a.x * b.x + a.y * b.y + a.z * b.z + a.w * b.w;
}
__device__ __forceinline__ void sth4(__half* p, float4 v) {
    uint2 raw;
    *(__half2*)&raw.x = __float22half2_rn(make_float2(v.x, v.y));
    *(__half2*)&raw.y = __float22half2_rn(make_float2(v.z, v.w));
    *(uint2*)p = raw;
}

// ---------------- CSR build -------------------------------------------------
__global__ void k_zero() {
    int i = blockIdx.x * blockDim.x + threadIdx.x;
    if (i < NN) g_deg[i] = 0;
}
__global__ void k_count(const int* __restrict__ dst) {
    int i = blockIdx.x * blockDim.x + threadIdx.x;
    if (i < EE) atomicAdd(&g_deg[dst[i]], 1);
}
__global__ void k_scan1() {
    __shared__ int s[1024];
    int i = blockIdx.x * 1024 + threadIdx.x;
    int v = (i < NN) ? g_deg[i] : 0;
    s[threadIdx.x] = v;
    __syncthreads();
#pragma unroll
    for (int off = 1; off < 1024; off <<= 1) {
        int t = (threadIdx.x >= off) ? s[threadIdx.x - off] : 0;
        __syncthreads();
        s[threadIdx.x] += t;
        __syncthreads();
    }
    if (i < NN) g_rowptr[i + 1] = s[threadIdx.x];
    if (threadIdx.x == 1023) g_bsum[blockIdx.x] = s[1023];
}
__global__ void k_scan2(int nb) {
    if (threadIdx.x == 0) {
        int run = 0;
        for (int b = 0; b < nb; b++) { int t = g_bsum[b]; g_bsum[b] = run; run += t; }
    }
}
__global__ void k_scan3() {
    int i = blockIdx.x * 1024 + threadIdx.x;
    if (i < NN) {
        int incl = g_rowptr[i + 1] + g_bsum[blockIdx.x];
        g_rowptr[i + 1] = incl;
        g_pos[i] = incl - g_deg[i];
    }
    if (i == 0) g_rowptr[0] = 0;
}
__global__ void k_fill(const int* __restrict__ src, const int* __restrict__ dst,
                       const int* __restrict__ rel) {
    int i = blockIdx.x * blockDim.x + threadIdx.x;
    if (i < EE) {
        int p = atomicAdd(&g_pos[dst[i]], 1);
        g_srcS[p] = src[i];
        g_relS[p] = rel[i];
    }
}

// ---------------- per-relation precompute ----------------------------------
__global__ void k_rhat(const float* __restrict__ rel_emb) {
    __shared__ float red[4];
    int r = blockIdx.x, t = threadIdx.x;
    float v = rel_emb[r * FF + t];
    float ss = warpSum(v * v);
    if ((t & 31) == 0) red[t >> 5] = ss;
    __syncthreads();
    float tot = red[0] + red[1] + red[2] + red[3];
    float invn = 1.0f / fmaxf(sqrtf(tot), 1e-12f);
    g_rhat[r * FF + t] = v * invn;
}
__global__ void k_scores(const float* __restrict__ ae, const float* __restrict__ ar) {
    int w = (blockIdx.x * blockDim.x + threadIdx.x) >> 5;
    int lane = threadIdx.x & 31;
    if (w >= 4 * RR) return;
    int t = w / RR, r = w % RR;
    const float* attn = ((t < 2) ? ae : ar) + (t & 1) * FF;
    float4 u = *(const float4*)&g_rhat[r * FF + lane * 4];
    float4 a = *(const float4*)&attn[lane * 4];
    float d = warpSum(dot4(u, a));
    if (lane == 0) g_sc[t * RR + r] = d;
}

// ---------------- gate kernel -> transposed fp16 -----------------------------
__global__ void k_cvtB(const float* __restrict__ ge, const float* __restrict__ gr) {
    int i = blockIdx.x * blockDim.x + threadIdx.x;
    if (i >= FDD * FDD) return;
    int k = i / FDD, n = i % FDD;
    g_Bt16[n * FDD + k] = __float2half(ge[i]);
    g_Bt16[FDD * FDD + n * FDD + k] = __float2half(gr[i]);
}

// ---------------- proxy prep: normalized fp16 [p][k] + raw transposed [j][p] -
__global__ void k_proxyPrep(const float* __restrict__ proxy_e,
                            const float* __restrict__ proxy_r) {
    __shared__ float red[4];
    int p = blockIdx.x, t = threadIdx.x;
    int dual = blockIdx.y;
    const float* proxy = dual ? proxy_r : proxy_e;
    float v0 = proxy[p * FDD + t];
    float v1 = proxy[p * FDD + 128 + t];
    float v2 = proxy[p * FDD + 256 + t];
    float ss = warpSum(v0 * v0 + v1 * v1 + v2 * v2);
    if ((t & 31) == 0) red[t >> 5] = ss;
    __syncthreads();
    float tot = red[0] + red[1] + red[2] + red[3];
    float invn = 1.0f / fmaxf(sqrtf(tot), 1e-12f);
    __half* phN = g_phN16 + (size_t)dual * PP * FDD + (size_t)p * FDD;
    phN[t]       = __float2half(v0 * invn);
    phN[128 + t] = __float2half(v1 * invn);
    phN[256 + t] = __float2half(v2 * invn);
    __half* prT = g_prT16 + (size_t)dual * FDD * PP;
    prT[t * PP + p]         = __float2half(v0);
    prT[(128 + t) * PP + p] = __float2half(v1);
    prT[(256 + t) * PP + p] = __float2half(v2);
}

// ---------------- initial features (R13 structure + fp16 copy) --------------
__global__ void k_init(const float* __restrict__ ent, const float* __restrict__ rel) {
    int w = (blockIdx.x * blockDim.x + threadIdx.x) >> 5;
    int lane = threadIdx.x & 31;
    if (w >= NN) return;
    int b = g_rowptr[w], e = g_rowptr[w + 1];
    float4 aE = make_float4(0, 0, 0, 0), aR = make_float4(0, 0, 0, 0);
    for (int i = b; i < e; i++) {
        int s = g_srcS[i], r = g_relS[i];
        float4 he = *(const float4*)&ent[(size_t)s * FF + lane * 4];
        float4 hr = *(const float4*)&rel[(size_t)r * FF + lane * 4];
        aE.x += he.x; aE.y += he.y; aE.z += he.z; aE.w += he.w;
        aR.x += hr.x; aR.y += hr.y; aR.z += hr.z; aR.w += hr.w;
    }
    float inv = 1.0f / fmaxf((float)(e - b), 1.0f);
    float4 oE = make_float4(tanhf(aE.x * inv), tanhf(aE.y * inv), tanhf(aE.z * inv), tanhf(aE.w * inv));
    float4 oR = make_float4(tanhf(aR.x * inv), tanhf(aR.y * inv), tanhf(aR.z * inv), tanhf(aR.w * inv));
    *(float4*)&g_outE[(size_t)w * FDD + lane * 4] = oE;
    *(float4*)&g_outR[(size_t)w * FDD + lane * 4] = oR;
    sth4(&g_o16[0][(size_t)w * FDD + lane * 4], oE);
    sth4(&g_o16[1][(size_t)w * FDD + lane * 4], oR);
}

// ---------------- fused dual-layer aggregation (R13 + fp16 copy) ------------
__device__ __forceinline__ void edgeUpdate(float4 h, float4 u, float d, float wgt,
                                           float4& acc) {
    float c = 2.0f * d * wgt;
    acc.x += wgt * h.x - c * u.x;
    acc.y += wgt * h.y - c * u.y;
    acc.z += wgt * h.z - c * u.z;
    acc.w += wgt * h.w - c * u.w;
}

__global__ void k_agg2(int layer) {
    int w = (blockIdx.x * blockDim.x + threadIdx.x) >> 5;
    int lane = threadIdx.x & 31;
    if (w >= NN) return;
    const float* finE = g_outE + layer * FF;
    float*       foutE = g_outE + (layer + 1) * FF;
    const float* finR = g_outR + layer * FF;
    float*       foutR = g_outR + (layer + 1) * FF;
    const float* scE = g_sc + layer * RR;
    const float* scR = g_sc + (2 + layer) * RR;
    int b = g_rowptr[w], e = g_rowptr[w + 1];
    float mE = -1e30f, mR = -1e30f;
    for (int i = b + lane; i < e; i += 32) {
        int r = g_relS[i];
        mE = fmaxf(mE, scE[r]);
        mR = fmaxf(mR, scR[r]);
    }
    mE = warpMax(mE); mR = warpMax(mR);
    float4 aE = make_float4(0, 0, 0, 0), aR = make_float4(0, 0, 0, 0);
    float wsE = 0.0f, wsR = 0.0f;
    int i = b;
    for (; i + 1 < e; i += 2) {
        int s0 = g_srcS[i],     r0 = g_relS[i];
        int s1 = g_srcS[i + 1], r1 = g_relS[i + 1];
        float4 u0  = *(const float4*)&g_rhat[(size_t)r0 * FF + lane * 4];
        float4 u1  = *(const float4*)&g_rhat[(size_t)r1 * FF + lane * 4];
        float4 h0E = *(const float4*)&finE[(size_t)s0 * FDD + lane * 4];
        float4 h1E = *(const float4*)&finE[(size_t)s1 * FDD + lane * 4];
        float4 h0R = *(const float4*)&finR[(size_t)s0 * FDD + lane * 4];
        float4 h1R = *(const float4*)&finR[(size_t)s1 * FDD + lane * 4];
        float d0E = dot4(h0E, u0), d0R = dot4(h0R, u0);
        float d1E = dot4(h1E, u1), d1R = dot4(h1R, u1);
        warpSum4(d0E, d0R, d1E, d1R);
        float w0E = __expf(scE[r0] - mE), w0R = __expf(scR[r0] - mR);
        float w1E = __expf(scE[r1] - mE), w1R = __expf(scR[r1] - mR);
        wsE += w0E; wsR += w0R;
        edgeUpdate(h0E, u0, d0E, w0E, aE);
        edgeUpdate(h0R, u0, d0R, w0R, aR);
        wsE += w1E; wsR += w1R;
        edgeUpdate(h1E, u1, d1E, w1E, aE);
        edgeUpdate(h1R, u1, d1R, w1R, aR);
    }
    if (i < e) {
        int s = g_srcS[i], r = g_relS[i];
        float4 u  = *(const float4*)&g_rhat[(size_t)r * FF + lane * 4];
        float4 hE = *(const float4*)&finE[(size_t)s * FDD + lane * 4];
        float4 hR = *(const float4*)&finR[(size_t)s * FDD + lane * 4];
        float dE = dot4(hE, u), dR = dot4(hR, u);
        float z0 = 0.0f, z1 = 0.0f;
        warpSum4(dE, dR, z0, z1);
        float wE = __expf(scE[r] - mE);
        float wR = __expf(scR[r] - mR);
        wsE += wE; wsR += wR;
        edgeUpdate(hE, u, dE, wE, aE);
        edgeUpdate(hR, u, dR, wR, aR);
    }
    float iE = (e > b) ? (1.0f / wsE) : 0.0f;
    float iR = (e > b) ? (1.0f / wsR) : 0.0f;
    float4 oE = make_float4(tanhf(aE.x * iE), tanhf(aE.y * iE), tanhf(aE.z * iE), tanhf(aE.w * iE));
    float4 oR = make_float4(tanhf(aR.x * iR), tanhf(aR.y * iR), tanhf(aR.z * iR), tanhf(aR.w * iR));
    *(float4*)&foutE[(size_t)w * FDD + lane * 4] = oE;
    *(float4*)&foutR[(size_t)w * FDD + lane * 4] = oR;
    int colOff = (layer + 1) * FF;
    sth4(&g_o16[0][(size_t)w * FDD + colOff + lane * 4], oE);
    sth4(&g_o16[1][(size_t)w * FDD + colOff + lane * 4], oR);
}

// ---------------- per-row inverse norms of outputs --------------------------
__global__ void k_norms() {
    int w = blockIdx.x * 8 + (threadIdx.x >> 5);
    int lane = threadIdx.x & 31;
    int dual = blockIdx.y;
    const float* Of = dual ? g_outR : g_outE;
    float ss = 0.0f;
#pragma unroll
    for (int c = 0; c < 3; c++) {
        float4 v = *(const float4*)&Of[(size_t)w * FDD + c * 128 + lane * 4];
        ss += dot4(v, v);
    }
    ss = warpSum(ss);
    if (lane == 0) g_invn[dual * NN + w] = 1.0f / fmaxf(sqrtf(ss), 1e-12f);
}

// ---------------- shared GEMM machinery --------------------------------------
#define STRD 72
#define LDM4(r, addr) \
    asm volatile("ldmatrix.sync.aligned.m8n8.x4.shared.b16 {%0,%1,%2,%3}, [%4];" \
        : "=r"((r)[0]), "=r"((r)[1]), "=r"((r)[2]), "=r"((r)[3]) : "r"(addr))
#define CP_COMMIT() asm volatile("cp.async.commit_group;" ::: "memory")
#define CP_WAIT(n)  asm volatile("cp.async.wait_group %0;" :: "n"(n) : "memory")

__device__ __forceinline__ void cpAsync16(unsigned dst, const void* src, bool pred) {
    int sz = pred ? 16 : 0;
    asm volatile("cp.async.ca.shared.global [%0], [%1], 16, %2;"
                 :: "r"(dst), "l"(src), "r"(sz) : "memory");
}
__device__ __forceinline__ void mma16816h(float* c, const unsigned* a, const unsigned* b) {
    asm volatile(
        "mma.sync.aligned.m16n8k16.row.col.f32.f16.f16.f32 "
        "{%0,%1,%2,%3}, {%4,%5,%6,%7}, {%8,%9}, {%0,%1,%2,%3};"
        : "+f"(c[0]), "+f"(c[1]), "+f"(c[2]), "+f"(c[3])
        : "r"(a[0]), "r"(a[1]), "r"(a[2]), "r"(a[3]), "r"(b[0]), "r"(b[1]));
}

// 128-row tile load, 512 threads (2 iters)
__device__ __forceinline__ void cpTile512(unsigned sbase, const __half* __restrict__ src,
                                          int srcStride, int row0, int rowCap, int col0) {
#pragma unroll
    for (int it = 0; it < 2; it++) {
        int id = threadIdx.x + it * 512;
        int r = id >> 3, c = id & 7;
        int gr = row0 + r;
        bool ok = gr < rowCap;
        int grc = ok ? gr : 0;
        cpAsync16(sbase + (unsigned)((r * STRD + c * 8) * 2),
                  src + (size_t)grc * srcStride + col0 + c * 8, ok);
    }
}
// 128-row tile load, 256 threads (4 iters)
__device__ __forceinline__ void cpTileA256(unsigned sbase, const __half* __restrict__ src,
                                           int row0, int rowCap, int col0) {
#pragma unroll
    for (int it = 0; it < 4; it++) {
        int id = threadIdx.x + it * 256;
        int r = id >> 3, c = id & 7;
        int gr = row0 + r;
        bool ok = gr < rowCap;
        int grc = ok ? gr : 0;
        cpAsync16(sbase + (unsigned)((r * STRD + c * 8) * 2),
                  src + (size_t)grc * FDD + col0 + c * 8, ok);
    }
}
// 64-row tile load, 256 threads (2 iters)
__device__ __forceinline__ void cpTileB256(unsigned sbase, const __half* __restrict__ src,
                                           int col0) {
#pragma unroll
    for (int it = 0; it < 2; it++) {
        int id = threadIdx.x + it * 256;
        int r = id >> 3, c = id & 7;
        cpAsync16(sbase + (unsigned)((r * STRD + c * 8) * 2),
                  src + (size_t)r * FDD + col0 + c * 8, true);
    }
}

// ---------------- k_plog: logits GEMM + softmax -> att16 --------------------
#define PLOG_ATILE (128 * STRD * 2)        // 18432 B
#define PLOG_BTILE (64 * STRD * 2)         // 9216 B
#define PLOG_STAGE (PLOG_ATILE + PLOG_BTILE)
#define GSMP (2 * PLOG_STAGE)              // 55296 B

__global__ void __launch_bounds__(256, 1) k_plog() {
    extern __shared__ __half dsm[];
    __shared__ float sInv[128];
    unsigned smb = smem_u32(dsm);
    int tid = threadIdx.x, wid = tid >> 5, lane = tid & 31;
    int m0 = blockIdx.x * 128;
    int dualSel = blockIdx.y;
    const __half* A16 = g_o16[dualSel];
    const __half* B16 = g_phN16 + (size_t)dualSel * PP * FDD;
    int wm = wid & 3, wn = wid >> 2;   // wn in {0,1}

    unsigned aRow = (unsigned)(wm * 32 + (lane & 15));
    unsigned aCol = (unsigned)((lane >> 4) * 8);
    unsigned bRow = (unsigned)(wn * 32 + (lane & 7) + ((lane >> 4) * 8));
    unsigned bCol = (unsigned)(((lane >> 3) & 1) * 8);
    unsigned offA = (aRow * STRD + aCol) * 2;
    unsigned offB = (bRow * STRD + bCol) * 2;

    float acc[2][4][4];
#pragma unroll
    for (int mt = 0; mt < 2; mt++)
#pragma unroll
        for (int nt = 0; nt < 4; nt++)
#pragma unroll
            for (int q = 0; q < 4; q++) acc[mt][nt][q] = 0.0f;

    cpTileA256(smb, A16, m0, NN, 0);
    cpTileB256(smb + PLOG_ATILE, B16, 0);
    CP_COMMIT();

    for (int kc = 0; kc < 6; kc++) {
        int s = kc & 1;
        if (kc + 1 < 6) {
            unsigned sb = smb + (unsigned)((s ^ 1) * PLOG_STAGE);
            int col0 = (kc + 1) * 64;
            cpTileA256(sb, A16, m0, NN, col0);
            cpTileB256(sb + PLOG_ATILE, B16, col0);
            CP_COMMIT();
            CP_WAIT(1);
        } else {
            CP_WAIT(0);
        }
        __syncthreads();
        unsigned sb = smb + (unsigned)(s * PLOG_STAGE);
        unsigned baseA = sb, baseB = sb + PLOG_ATILE;
#pragma unroll
        for (int ks = 0; ks < 4; ks++) {
            unsigned kb = (unsigned)(ks * 32);
            unsigned a[2][4], bf[4][2];
#pragma unroll
            for (int mt = 0; mt < 2; mt++)
                LDM4(a[mt], baseA + offA + (unsigned)(mt * 16 * STRD * 2) + kb);
#pragma unroll
            for (int p = 0; p < 2; p++) {
                unsigned r[4];
                LDM4(r, baseB + offB + (unsigned)(p * 16 * STRD * 2) + kb);
                bf[2 * p][0] = r[0]; bf[2 * p][1] = r[1];
                bf[2 * p + 1][0] = r[2]; bf[2 * p + 1][1] = r[3];
            }
#pragma unroll
            for (int mt = 0; mt < 2; mt++)
#pragma unroll
                for (int nt = 0; nt < 4; nt++)
                    mma16816h(acc[mt][nt], a[mt], bf[nt]);
        }
        __syncthreads();
    }

    // stage logits to smem (stride 65 floats)
    float* sT = (float*)dsm;
    int lr = lane >> 2, lc = lane & 3;
#pragma unroll
    for (int mt = 0; mt < 2; mt++)
#pragma unroll
        for (int h = 0; h < 2; h++) {
            int rowl = wm * 32 + mt * 16 + lr + h * 8;
#pragma unroll
            for (int nt = 0; nt < 4; nt++) {
                int coll = wn * 32 + nt * 8 + lc * 2;
                sT[rowl * 65 + coll]     = acc[mt][nt][h * 2 + 0];
                sT[rowl * 65 + coll + 1] = acc[mt][nt][h * 2 + 1];
            }
        }
    __syncthreads();

    // softmax per row (threads 0..127)
    if (tid < 128) {
        int row = m0 + tid;
        float inv = (row < NN) ? g_invn[dualSel * NN + row] : 0.0f;
        float mx = -1e30f;
#pragma unroll 8
        for (int c = 0; c < 64; c++) {
            float v = sT[tid * 65 + c] * inv;
            sT[tid * 65 + c] = v;
            mx = fmaxf(mx, v);
        }
        float ssum = 0.0f;
#pragma unroll 8
        for (int c = 0; c < 64; c++) {
            float e = __expf(sT[tid * 65 + c] - mx);
            sT[tid * 65 + c] = e;
            ssum += e;
        }
        sInv[tid] = 1.0f / ssum;
    }
    __syncthreads();

    // coalesced att16 writeback: 128 rows x 32 half2
#pragma unroll
    for (int k = 0; k < 16; k++) {
        int id = tid + k * 256;
        int row = id >> 5, c2 = id & 31;
        int gr = m0 + row;
        if (gr < NN) {
            float iv = sInv[row];
            float e0 = sT[row * 65 + c2 * 2], e1 = sT[row * 65 + c2 * 2 + 1];
            *(__half2*)&g_att16[((size_t)dualSel * NN + gr) * PP + c2 * 2] =
                __floats2half2_rn(e0 * iv, e1 * iv);
        }
    }
}

// ---------------- k_pf2: pf = outputs - att @ proxy (HMMA, K=64) -------------
#define PF2_TILE (128 * STRD * 2)          // 18432 B per tile
#define GSMF 67584                          // epilogue 128x132 fp32

__global__ void __launch_bounds__(512, 1) k_pf2() {
    extern __shared__ __half dsm[];
    unsigned smb = smem_u32(dsm);
    int tid = threadIdx.x, wid = tid >> 5, lane = tid & 31;
    int m0 = blockIdx.x * 128, j0 = blockIdx.y * 128;
    int dualSel = blockIdx.z;
    size_t doff = (size_t)dualSel * NN * FDD;
    const __half* A16 = g_att16 + (size_t)dualSel * NN * PP;
    const __half* B16 = g_prT16 + (size_t)dualSel * FDD * PP;
    int wm = wid & 3, wn = wid >> 2;

    unsigned aRow = (unsigned)(wm * 32 + (lane & 15));
    unsigned aCol = (unsigned)((lane >> 4) * 8);
    unsigned bRow = (unsigned)(wn * 32 + (lane & 7) + ((lane >> 4) * 8));
    unsigned bCol = (unsigned)(((lane >> 3) & 1) * 8);
    unsigned offA = (aRow * STRD + aCol) * 2;
    unsigned offB = (bRow * STRD + bCol) * 2;

    float acc[2][4][4];
#pragma unroll
    for (int mt = 0; mt < 2; mt++)
#pragma unroll
        for (int nt = 0; nt < 4; nt++)
#pragma unroll
            for (int q = 0; q < 4; q++) acc[mt][nt][q] = 0.0f;

    cpTile512(smb, A16, PP, m0, NN, 0);
    cpTile512(smb + PF2_TILE, B16, PP, j0, FDD, 0);
    CP_COMMIT();
    CP_WAIT(0);
    __syncthreads();

    unsigned baseA = smb, baseB = smb + PF2_TILE;
#pragma unroll
    for (int ks = 0; ks < 4; ks++) {
        unsigned kb = (unsigned)(ks * 32);
        unsigned a[2][4], bf[4][2];
#pragma unroll
        for (int mt = 0; mt < 2; mt++)
            LDM4(a[mt], baseA + offA + (unsigned)(mt * 16 * STRD * 2) + kb);
#pragma unroll
        for (int p = 0; p < 2; p++) {
            unsigned r[4];
            LDM4(r, baseB + offB + (unsigned)(p * 16 * STRD * 2) + kb);
            bf[2 * p][0] = r[0]; bf[2 * p][1] = r[1];
            bf[2 * p + 1][0] = r[2]; bf[2 * p + 1][1] = r[3];
        }
#pragma unroll
        for (int mt = 0; mt < 2; mt++)
#pragma unroll
            for (int nt = 0; nt < 4; nt++)
                mma16816h(acc[mt][nt], a[mt], bf[nt]);
    }
    __syncthreads();

    // stage acc, then coalesced pf = out - acc
    float* sT = (float*)dsm;
    int lr = lane >> 2, lc = lane & 3;
#pragma unroll
    for (int mt = 0; mt < 2; mt++)
#pragma unroll
        for (int h = 0; h < 2; h++) {
            int rowl = wm * 32 + mt * 16 + lr + h * 8;
#pragma unroll
            for (int nt = 0; nt < 4; nt++) {
                int coll = wn * 32 + nt * 8 + lc * 2;
                *(float2*)&sT[rowl * 132 + coll] =
                    make_float2(acc[mt][nt][h * 2 + 0], acc[mt][nt][h * 2 + 1]);
            }
        }
    __syncthreads();

    const float* O = dualSel ? g_outR : g_outE;
#pragma unroll
    for (int rr = 0; rr < 8; rr++) {
        int rowl = wid * 8 + rr;
        int row = m0 + rowl;
        if (row < NN) {
            int col = j0 + lane * 4;
            float4 t4 = *(const float4*)&sT[rowl * 132 + lane * 4];
            float4 o4 = *(const float4*)&O[(size_t)row * FDD + col];
            float4 r;
            r.x = o4.x - t4.x;
            r.y = o4.y - t4.y;
            r.z = o4.z - t4.z;
            r.w = o4.w - t4.w;
            size_t idx = doff + (size_t)row * FDD + col;
            *(float4*)&g_pf[idx] = r;
            sth4(&g_pf16[idx], r);
        }
    }
}

// ---------------- gate GEMM (unchanged from R13) ----------------------------
__device__ __forceinline__ float gateCombine(float t, float b, float o, float p) {
    float g = 1.0f / (1.0f + __expf(-(t + b)));
    return g * o + (1.0f - g) * p;
}

#define TSZ  (128 * STRD)
#define STAGEB (2 * TSZ * 2)
#define GSM_BYTES (2 * STAGEB)            // 73728 B
#define ESTRD 132

__global__ void __launch_bounds__(512, 1) k_gemm4(const float* __restrict__ bias_e,
                                                  const float* __restrict__ bias_r,
                                                  float* __restrict__ out) {
    extern __shared__ __half sm[];
    unsigned smb = smem_u32(sm);
    int tid = threadIdx.x, wid = tid >> 5, lane = tid & 31;
    int m0 = blockIdx.x * 128, j0 = blockIdx.y * 128;
    int dualSel = blockIdx.z;
    const float* bias = dualSel ? bias_r : bias_e;
    size_t doff = (size_t)dualSel * NN * FDD;
    const __half* A16 = g_pf16 + doff;
    const __half* B16 = g_Bt16 + (size_t)dualSel * FDD * FDD;
    int wm = wid & 3, wn = wid >> 2;

    unsigned aRow = (unsigned)(wm * 32 + (lane & 15));
    unsigned aCol = (unsigned)((lane >> 4) * 8);
    unsigned bRow = (unsigned)(wn * 32 + (lane & 7) + ((lane >> 4) * 8));
    unsigned bCol = (unsigned)(((lane >> 3) & 1) * 8);
    unsigned offA = (aRow * STRD + aCol) * 2;
    unsigned offB = (bRow * STRD + bCol) * 2;

    float acc[2][4][4];
#pragma unroll
    for (int mt = 0; mt < 2; mt++)
#pragma unroll
        for (int nt = 0; nt < 4; nt++)
#pragma unroll
            for (int q = 0; q < 4; q++) acc[mt][nt][q] = 0.0f;

    cpTile512(smb, A16, FDD, m0, NN, 0);
    cpTile512(smb + TSZ * 2, B16, FDD, j0, FDD, 0);
    CP_COMMIT();

    for (int kc = 0; kc < 6; kc++) {
        int s = kc & 1;
        if (kc + 1 < 6) {
            unsigned sb = smb + (unsigned)((s ^ 1) * STAGEB);
            int col0 = (kc + 1) * 64;
            cpTile512(sb, A16, FDD, m0, NN, col0);
            cpTile512(sb + TSZ * 2, B16, FDD, j0, FDD, col0);
            CP_COMMIT();
            CP_WAIT(1);
        } else {
            CP_WAIT(0);
        }
        __syncthreads();

        unsigned sb = smb + (unsigned)(s * STAGEB);
        unsigned baseA = sb, baseB = sb + TSZ * 2;
#pragma unroll
        for (int ks = 0; ks < 4; ks++) {
            unsigned kb = (unsigned)(ks * 32);
            unsigned a[2][4], bf[4][2];
#pragma unroll
            for (int mt = 0; mt < 2; mt++)
                LDM4(a[mt], baseA + offA + (unsigned)(mt * 16 * STRD * 2) + kb);
#pragma unroll
            for (int p = 0; p < 2; p++) {
                unsigned r[4];
                LDM4(r, baseB + offB + (unsigned)(p * 16 * STRD * 2) + kb);
                bf[2 * p][0] = r[0]; bf[2 * p][1] = r[1];
                bf[2 * p + 1][0] = r[2]; bf[2 * p + 1][1] = r[3];
            }
#pragma unroll
            for (int mt = 0; mt < 2; mt++)
#pragma unroll
                for (int nt = 0; nt < 4; nt++)
                    mma16816h(acc[mt][nt], a[mt], bf[nt]);
        }
        __syncthreads();
    }

    float* sT = (float*)sm;
    int lr = lane >> 2, lc = lane & 3;
#pragma unroll
    for (int mt = 0; mt < 2; mt++)
#pragma unroll
        for (int h = 0; h < 2; h++) {
            int rowl = wm * 32 + mt * 16 + lr + h * 8;
#pragma unroll
            for (int nt = 0; nt < 4; nt++) {
                int coll = wn * 32 + nt * 8 + lc * 2;
                *(float2*)&sT[rowl * ESTRD + coll] =
                    make_float2(acc[mt][nt][h * 2 + 0], acc[mt][nt][h * 2 + 1]);
            }
        }
    __syncthreads();

    const float* O = dualSel ? g_outR : g_outE;
    float4 b4 = *(const float4*)&bias[j0 + lane * 4];
#pragma unroll
    for (int rr = 0; rr < 8; rr++) {
        int rowl = wid * 8 + rr;
        int row = m0 + rowl;
        if (row < NN) {
            int col = j0 + lane * 4;
            float4 t4 = *(const float4*)&sT[rowl * ESTRD + lane * 4];
            float4 o4 = *(const float4*)&O[(size_t)row * FDD + col];
            float4 p4 = *(const float4*)&g_pf[doff + (size_t)row * FDD + col];
            float4 r;
            r.x = gateCombine(t4.x, b4.x, o4.x, p4.x);
            r.y = gateCombine(t4.y, b4.y, o4.y, p4.y);
            r.z = gateCombine(t4.z, b4.z, o4.z, p4.z);
            r.w = gateCombine(t4.w, b4.w, o4.w, p4.w);
            *(float4*)&out[(size_t)row * (2 * FDD) + dualSel * FDD + col] = r;
        }
    }
}

// ---------------- launch -----------------------------------------------------
extern "C" void kernel_launch(void* const* d_in, const int* in_sizes, int n_in,
                              void* d_out, int out_size) {
    const float* ent     = (const float*)d_in[0];
    const float* rel     = (const float*)d_in[1];
    const int*   esrc    = (const int*)d_in[2];
    const int*   edst    = (const int*)d_in[3];
    const int*   erel    = (const int*)d_in[4];
    const float* attn_e  = (const float*)d_in[5];
    const float* gate_e  = (const float*)d_in[6];
    const float* proxy_e = (const float*)d_in[7];
    const float* bias_e  = (const float*)d_in[8];
    const float* attn_r  = (const float*)d_in[9];
    const float* gate_r  = (const float*)d_in[10];
    const float* proxy_r = (const float*)d_in[11];
    const float* bias_r  = (const float*)d_in[12];
    float* out = (float*)d_out;

    cudaFuncSetAttribute(k_plog,  cudaFuncAttributeMaxDynamicSharedMemorySize, GSMP);
    cudaFuncSetAttribute(k_pf2,   cudaFuncAttributeMaxDynamicSharedMemorySize, GSMF);
    cudaFuncSetAttribute(k_gemm4, cudaFuncAttributeMaxDynamicSharedMemorySize, GSM_BYTES);

    const int nb = (NN + 1023) / 1024;
    k_zero<<<(NN + 255) / 256, 256>>>();
    k_count<<<(EE + 255) / 256, 256>>>(edst);
    k_scan1<<<nb, 1024>>>();
    k_scan2<<<1, 32>>>(nb);
    k_scan3<<<nb, 1024>>>();
    k_fill<<<(EE + 255) / 256, 256>>>(esrc, edst, erel);
    k_rhat<<<RR, 128>>>(rel);
    k_scores<<<(4 * RR * 32 + 255) / 256, 256>>>(attn_e, attn_r);
    k_cvtB<<<(FDD * FDD + 255) / 256, 256>>>(gate_e, gate_r);
    k_proxyPrep<<<dim3(PP, 2), 128>>>(proxy_e, proxy_r);
    k_init<<<(NN + 7) / 8, 256>>>(ent, rel);
    k_agg2<<<(NN + 7) / 8, 256>>>(0);
    k_agg2<<<(NN + 7) / 8, 256>>>(1);

    const int mtiles = (NN + 127) / 128;   // 391
    k_norms<<<dim3(NN / 8, 2), 256>>>();
    k_plog<<<dim3(mtiles, 2), 256, GSMP>>>();
    k_pf2<<<dim3(mtiles, FDD / 128, 2), 512, GSMF>>>();
    k_gemm4<<<dim3(mtiles, FDD / 128, 2), 512, GSM_BYTES>>>(bias_e, bias_r, out);
}